// round 4
// baseline (speedup 1.0000x reference)
#include <cuda_runtime.h>
#include <math.h>

// SO3_Rotation, single fused kernel:
//  - 16 elements per 256-thread block; threads 0..15 each build their element's
//    165 Wigner-D entries in closed form (template-unrolled, compile-time
//    coefficients) directly into shared memory.
//  - All threads prefetch their l=4 embedding block (9 float4) before the
//    barrier so DRAM stays busy while D is computed.
//  - Apply: each thread owns 4 channels (float4) of one element, computes all
//    25 rows; emb global->reg directly, D broadcast from smem.

#define NROWS 25
#define NCH   64
#define ETILE 1600
#define NDTOT 165
#define EPB   16
#define DPITCH 166

// ---------------- compile-time helpers ----------------
__host__ __device__ constexpr double cfact(int n){ double r=1.0; for(int i=2;i<=n;++i) r*=(double)i; return r; }
__host__ __device__ constexpr double csqrt_(double x){ double r = (x>1.0)?x:1.0; for(int i=0;i<100;++i) r = 0.5*(r + x/r); return r; }
__host__ __device__ constexpr int cmax(int a,int b){ return a>b?a:b; }
__host__ __device__ constexpr int cmin(int a,int b){ return a<b?a:b; }
__host__ __device__ constexpr bool nzB(int x,int y){
    return (x>0&&y>0)||(x<0&&y<0)||(x==0&&y>=0)||(x>0&&y==0);
}

template<int L,int P,int Q,int K,bool Done>
struct DTerm {
    static constexpr float coef = (float)(
        ((((P-Q+K)&1)? -1.0 : 1.0) *
         csqrt_(cfact(L+P)*cfact(L-P)*cfact(L+Q)*cfact(L-Q)) /
         (cfact(L+Q-K)*cfact(K)*cfact(P-Q+K)*cfact(L-P-K))));
    __device__ static __forceinline__ float eval(const float* chp, const float* shp){
        constexpr int K1 = cmin(L+Q, L-P);
        return fmaf(coef, chp[2*L+Q-P-2*K]*shp[P-Q+2*K],
                    DTerm<L,P,Q,K+1,(K+1>K1)>::eval(chp,shp));
    }
};
template<int L,int P,int Q,int K>
struct DTerm<L,P,Q,K,true> {
    __device__ static __forceinline__ float eval(const float*, const float*){ return 0.f; }
};

template<int L,int P,int Q>
__device__ __forceinline__ float dval(const float* chp, const float* shp){
    constexpr int K0 = cmax(0, Q-P);
    constexpr int K1 = cmin(L+Q, L-P);
    return DTerm<L,P,Q,K0,(K0>K1)>::eval(chp,shp);
}

template<int L,int X,int Y>
__device__ __forceinline__ float Bval(const float* chp, const float* shp){
    if constexpr (X>0 && Y>0){
        constexpr float s1 = ((X+Y)&1)? -1.f : 1.f;
        constexpr float s2 = (X&1)? -1.f : 1.f;
        return s1*dval<L,X,Y>(chp,shp) + s2*dval<L,X,-Y>(chp,shp);
    } else if constexpr (X<0 && Y<0){
        constexpr int P=-X, Q=-Y;
        constexpr float s1 = ((P+Q)&1)? -1.f : 1.f;
        constexpr float s2 = (P&1)? -1.f : 1.f;
        return s1*dval<L,P,Q>(chp,shp) - s2*dval<L,P,-Q>(chp,shp);
    } else if constexpr (X==0 && Y==0){
        return dval<L,0,0>(chp,shp);
    } else if constexpr (X==0 && Y>0){
        constexpr float s = ((Y&1)? -1.f : 1.f) * 1.41421356237309515f;
        return s*dval<L,0,Y>(chp,shp);
    } else if constexpr (X>0 && Y==0){
        constexpr float s = ((X&1)? -1.f : 1.f) * 1.41421356237309515f;
        return s*dval<L,X,0>(chp,shp);
    } else {
        return 0.f;
    }
}

struct Trig { float cat[5], sat[5], cgt[5], sgt[5]; };

template<int L,int OFF,int IJ,bool Done>
struct DLoop {
    __device__ static __forceinline__ void run(float* __restrict__ base,
            const float* chp, const float* shp, const Trig& T){
        constexpr int N1 = 2*L+1;
        constexpr int I = IJ / N1, J = IJ % N1;
        constexpr int MA = I - L, NB = J - L;
        constexpr int P = MA<0 ? -MA : MA;
        constexpr int Q = NB<0 ? -NB : NB;
        float rc = T.cat[P];
        float rs = (MA>0) ? -T.sat[P] : T.sat[P];
        float cc = T.cgt[Q];
        float cs = (NB>0) ? T.sgt[Q] : -T.sgt[Q];
        float acc = 0.f;
        if constexpr (nzB(MA,NB))
            acc = fmaf(rc*cc, Bval<L,MA,NB>(chp,shp), acc);
        if constexpr (NB!=0){ if constexpr (nzB(MA,-NB))
            acc = fmaf(rc*cs, Bval<L,MA,(NB!=0)?-NB:0>(chp,shp), acc); }
        if constexpr (MA!=0){ if constexpr (nzB(-MA,NB))
            acc = fmaf(rs*cc, Bval<L,(MA!=0)?-MA:0,NB>(chp,shp), acc); }
        if constexpr (MA!=0 && NB!=0){ if constexpr (nzB(-MA,-NB))
            acc = fmaf(rs*cs, Bval<L,(MA!=0)?-MA:0,(NB!=0)?-NB:0>(chp,shp), acc); }
        base[OFF+IJ] = acc;
        DLoop<L,OFF,IJ+1,(IJ+1==N1*N1)>::run(base, chp, shp, T);
    }
};
template<int L,int OFF,int IJ>
struct DLoop<L,OFF,IJ,true>{
    __device__ static __forceinline__ void run(float*, const float*, const float*, const Trig&){}
};

// ---------------- apply helper (l = 0..3, loads from global) ----------------
template<int L, int B0, int DOFF>
__device__ __forceinline__ void applyL(const float* __restrict__ sDe,
                                       const float* __restrict__ ebase,
                                       float* __restrict__ obase)
{
    constexpr int N1 = 2*L+1;
    float4 eR[N1];
    #pragma unroll
    for (int j=0;j<N1;j++)
        eR[j] = *(const float4*)(ebase + (B0+j)*NCH);
    #pragma unroll
    for (int i=0;i<N1;i++){
        float4 a;
        float d0 = sDe[DOFF + i*N1];
        a.x = d0*eR[0].x; a.y = d0*eR[0].y; a.z = d0*eR[0].z; a.w = d0*eR[0].w;
        #pragma unroll
        for (int j=1;j<N1;j++){
            float d = sDe[DOFF + i*N1 + j];
            a.x = fmaf(d, eR[j].x, a.x);
            a.y = fmaf(d, eR[j].y, a.y);
            a.z = fmaf(d, eR[j].z, a.z);
            a.w = fmaf(d, eR[j].w, a.w);
        }
        *(float4*)(obase + (B0+i)*NCH) = a;
    }
}

// ---------------- fused kernel ----------------
__global__ void __launch_bounds__(256)
so3_fused(const float* __restrict__ rot,
          const float* __restrict__ emb,
          float* __restrict__ out, int E)
{
    __shared__ float sD[EPB * DPITCH];
    const int tid    = threadIdx.x;
    const int e0     = blockIdx.x * EPB;
    const int el     = tid >> 4;
    const int lane16 = tid & 15;
    const int e      = e0 + el;
    const bool valid = (e < E);

    const size_t off = (size_t)e * ETILE + lane16 * 4;
    const float* eb  = emb + off;
    float*       ob  = out + off;

    // prefetch l=4 block (keeps DRAM busy during D-gen)
    float4 e4[9];
    if (valid) {
        #pragma unroll
        for (int j=0;j<9;j++)
            e4[j] = *(const float4*)(eb + (16+j)*NCH);
    }

    // threads 0..15: build D for element e0+tid into smem
    if (tid < EPB && (e0 + tid) < E) {
        const float* R = rot + (size_t)(e0 + tid) * 9;
        float r00=R[0], r01=R[1], r02=R[2];
        float r11=R[4];
        float r20=R[6], r21=R[7], r22=R[8];

        float x0=r01, x1=r11, x2=r21;
        float inv = rsqrtf(x0*x0 + x1*x1 + x2*x2);
        x0*=inv; x1*=inv; x2*=inv;
        x0 = fminf(1.f, fmaxf(-1.f, x0));
        x1 = fminf(1.f, fmaxf(-1.f, x1));
        x2 = fminf(1.f, fmaxf(-1.f, x2));
        float cb = x1;
        float rxz = sqrtf(x0*x0 + x2*x2);
        float ca, sa;
        if (rxz > 1e-20f){ ca = x2/rxz; sa = x0/rxz; } else { ca = 1.f; sa = 0.f; }
        float gy = ca*r02 - sa*r22;
        float gx = ca*r00 - sa*r20;
        float gr = sqrtf(gx*gx + gy*gy);
        float cg, sg;
        if (gr > 1e-20f){ cg = gx/gr; sg = gy/gr; } else { cg = 1.f; sg = 0.f; }

        float ch = sqrtf(fmaxf(0.f, 0.5f*(1.f+cb)));
        float sh = sqrtf(fmaxf(0.f, 0.5f*(1.f-cb)));
        float chp[9], shp[9];
        chp[0]=1.f; shp[0]=1.f;
        #pragma unroll
        for (int k=1;k<9;k++){ chp[k]=chp[k-1]*ch; shp[k]=shp[k-1]*sh; }

        Trig T;
        T.cat[0]=1.f; T.sat[0]=0.f; T.cgt[0]=1.f; T.sgt[0]=0.f;
        #pragma unroll
        for (int k=1;k<5;k++){
            float c0=T.cat[k-1], s0=T.sat[k-1];
            T.cat[k]=c0*ca - s0*sa;  T.sat[k]=s0*ca + c0*sa;
            float c1=T.cgt[k-1], s1=T.sgt[k-1];
            T.cgt[k]=c1*cg - s1*sg;  T.sgt[k]=s1*cg + c1*sg;
        }

        float* base = sD + tid * DPITCH;
        DLoop<0,  0, 0, false>::run(base, chp, shp, T);
        DLoop<1,  1, 0, false>::run(base, chp, shp, T);
        DLoop<2, 10, 0, false>::run(base, chp, shp, T);
        DLoop<3, 35, 0, false>::run(base, chp, shp, T);
        DLoop<4, 84, 0, false>::run(base, chp, shp, T);
    }
    __syncthreads();

    if (!valid) return;
    const float* sDe = sD + el * DPITCH;

    // l=4 using prefetched registers
    {
        #pragma unroll
        for (int i=0;i<9;i++){
            float4 a;
            float d0 = sDe[84 + i*9];
            a.x = d0*e4[0].x; a.y = d0*e4[0].y; a.z = d0*e4[0].z; a.w = d0*e4[0].w;
            #pragma unroll
            for (int j=1;j<9;j++){
                float d = sDe[84 + i*9 + j];
                a.x = fmaf(d, e4[j].x, a.x);
                a.y = fmaf(d, e4[j].y, a.y);
                a.z = fmaf(d, e4[j].z, a.z);
                a.w = fmaf(d, e4[j].w, a.w);
            }
            *(float4*)(ob + (16+i)*NCH) = a;
        }
    }
    applyL<3, 9, 35>(sDe, eb, ob);
    applyL<2, 4, 10>(sDe, eb, ob);
    applyL<1, 1,  1>(sDe, eb, ob);
    applyL<0, 0,  0>(sDe, eb, ob);
}

extern "C" void kernel_launch(void* const* d_in, const int* in_sizes, int n_in,
                              void* d_out, int out_size)
{
    const float* rot = (const float*)d_in[0];   // (E,3,3)
    const float* emb = (const float*)d_in[1];   // (E,25,64)
    float* out = (float*)d_out;                 // (E,25,64)
    int E = in_sizes[0] / 9;
    so3_fused<<<(E + EPB - 1) / EPB, 256>>>(rot, emb, out, E);
}

// round 5
// speedup vs baseline: 1.0656x; 1.0656x over previous
#include <cuda_runtime.h>
#include <math.h>

// SO3_Rotation, two kernels:
//  A) so3_dgen : 4 threads per element build the 165 Wigner-D entries in
//     closed form (template-unrolled, compile-time coefficients) into smem,
//     then coalesced flush to g_D[k*E+e] (transposed, L2-resident).
//  B) so3_apply: 8 elements per 128-thread block (high blocks/SM for MLP);
//     each thread owns 4 channels (float4) of one element, computes 25 rows.
//     emb global->reg directly; D broadcast from smem.

#define NROWS 25
#define NCH   64
#define ETILE 1600
#define NDTOT 165
#define EMAX  50048
#define EPB   8            // elements per apply block
#define GEPB  32           // elements per dgen block
#define DPITCH 166

__device__ float g_D[(size_t)NDTOT * EMAX];

// ---------------- compile-time helpers ----------------
__host__ __device__ constexpr double cfact(int n){ double r=1.0; for(int i=2;i<=n;++i) r*=(double)i; return r; }
__host__ __device__ constexpr double csqrt_(double x){ double r = (x>1.0)?x:1.0; for(int i=0;i<100;++i) r = 0.5*(r + x/r); return r; }
__host__ __device__ constexpr int cmax(int a,int b){ return a>b?a:b; }
__host__ __device__ constexpr int cmin(int a,int b){ return a<b?a:b; }
__host__ __device__ constexpr bool nzB(int x,int y){
    return (x>0&&y>0)||(x<0&&y<0)||(x==0&&y>=0)||(x>0&&y==0);
}

template<int L,int P,int Q,int K,bool Done>
struct DTerm {
    static constexpr float coef = (float)(
        ((((P-Q+K)&1)? -1.0 : 1.0) *
         csqrt_(cfact(L+P)*cfact(L-P)*cfact(L+Q)*cfact(L-Q)) /
         (cfact(L+Q-K)*cfact(K)*cfact(P-Q+K)*cfact(L-P-K))));
    __device__ static __forceinline__ float eval(const float* chp, const float* shp){
        constexpr int K1 = cmin(L+Q, L-P);
        return fmaf(coef, chp[2*L+Q-P-2*K]*shp[P-Q+2*K],
                    DTerm<L,P,Q,K+1,(K+1>K1)>::eval(chp,shp));
    }
};
template<int L,int P,int Q,int K>
struct DTerm<L,P,Q,K,true> {
    __device__ static __forceinline__ float eval(const float*, const float*){ return 0.f; }
};

template<int L,int P,int Q>
__device__ __forceinline__ float dval(const float* chp, const float* shp){
    constexpr int K0 = cmax(0, Q-P);
    constexpr int K1 = cmin(L+Q, L-P);
    return DTerm<L,P,Q,K0,(K0>K1)>::eval(chp,shp);
}

template<int L,int X,int Y>
__device__ __forceinline__ float Bval(const float* chp, const float* shp){
    if constexpr (X>0 && Y>0){
        constexpr float s1 = ((X+Y)&1)? -1.f : 1.f;
        constexpr float s2 = (X&1)? -1.f : 1.f;
        return s1*dval<L,X,Y>(chp,shp) + s2*dval<L,X,-Y>(chp,shp);
    } else if constexpr (X<0 && Y<0){
        constexpr int P=-X, Q=-Y;
        constexpr float s1 = ((P+Q)&1)? -1.f : 1.f;
        constexpr float s2 = (P&1)? -1.f : 1.f;
        return s1*dval<L,P,Q>(chp,shp) - s2*dval<L,P,-Q>(chp,shp);
    } else if constexpr (X==0 && Y==0){
        return dval<L,0,0>(chp,shp);
    } else if constexpr (X==0 && Y>0){
        constexpr float s = ((Y&1)? -1.f : 1.f) * 1.41421356237309515f;
        return s*dval<L,0,Y>(chp,shp);
    } else if constexpr (X>0 && Y==0){
        constexpr float s = ((X&1)? -1.f : 1.f) * 1.41421356237309515f;
        return s*dval<L,X,0>(chp,shp);
    } else {
        return 0.f;
    }
}

struct Trig { float cat[5], sat[5], cgt[5], sgt[5]; };

// D-entry loop over IJ in [IJ, END)
template<int L,int OFF,int IJ,int END,bool Done>
struct DLoopR {
    __device__ static __forceinline__ void run(float* __restrict__ base,
            const float* chp, const float* shp, const Trig& T){
        constexpr int N1 = 2*L+1;
        constexpr int I = IJ / N1, J = IJ % N1;
        constexpr int MA = I - L, NB = J - L;
        constexpr int P = MA<0 ? -MA : MA;
        constexpr int Q = NB<0 ? -NB : NB;
        float rc = T.cat[P];
        float rs = (MA>0) ? -T.sat[P] : T.sat[P];
        float cc = T.cgt[Q];
        float cs = (NB>0) ? T.sgt[Q] : -T.sgt[Q];
        float acc = 0.f;
        if constexpr (nzB(MA,NB))
            acc = fmaf(rc*cc, Bval<L,MA,NB>(chp,shp), acc);
        if constexpr (NB!=0){ if constexpr (nzB(MA,-NB))
            acc = fmaf(rc*cs, Bval<L,MA,(NB!=0)?-NB:0>(chp,shp), acc); }
        if constexpr (MA!=0){ if constexpr (nzB(-MA,NB))
            acc = fmaf(rs*cc, Bval<L,(MA!=0)?-MA:0,NB>(chp,shp), acc); }
        if constexpr (MA!=0 && NB!=0){ if constexpr (nzB(-MA,-NB))
            acc = fmaf(rs*cs, Bval<L,(MA!=0)?-MA:0,(NB!=0)?-NB:0>(chp,shp), acc); }
        base[OFF+IJ] = acc;
        DLoopR<L,OFF,IJ+1,END,(IJ+1==END)>::run(base, chp, shp, T);
    }
};
template<int L,int OFF,int IJ,int END>
struct DLoopR<L,OFF,IJ,END,true>{
    __device__ static __forceinline__ void run(float*, const float*, const float*, const Trig&){}
};

// ---------------- kernel A: build D (4 threads / element) ----------------
__global__ void __launch_bounds__(128)
so3_dgen(const float* __restrict__ rot, int E)
{
    __shared__ float sD[GEPB * DPITCH];
    const int tid  = threadIdx.x;
    const int e0   = blockIdx.x * GEPB;
    const int el   = tid >> 2;        // 0..31
    const int slot = tid & 3;
    const int e    = e0 + el;

    if (e < E) {
        const float* R = rot + (size_t)e * 9;
        float r00=R[0], r01=R[1], r02=R[2];
        float r11=R[4];
        float r20=R[6], r21=R[7], r22=R[8];

        float x0=r01, x1=r11, x2=r21;
        float inv = rsqrtf(x0*x0 + x1*x1 + x2*x2);
        x0*=inv; x1*=inv; x2*=inv;
        x0 = fminf(1.f, fmaxf(-1.f, x0));
        x1 = fminf(1.f, fmaxf(-1.f, x1));
        x2 = fminf(1.f, fmaxf(-1.f, x2));
        float cb = x1;
        float rxz = sqrtf(x0*x0 + x2*x2);
        float ca, sa;
        if (rxz > 1e-20f){ ca = x2/rxz; sa = x0/rxz; } else { ca = 1.f; sa = 0.f; }
        float gy = ca*r02 - sa*r22;
        float gx = ca*r00 - sa*r20;
        float gr = sqrtf(gx*gx + gy*gy);
        float cg, sg;
        if (gr > 1e-20f){ cg = gx/gr; sg = gy/gr; } else { cg = 1.f; sg = 0.f; }

        float ch = sqrtf(fmaxf(0.f, 0.5f*(1.f+cb)));
        float sh = sqrtf(fmaxf(0.f, 0.5f*(1.f-cb)));
        float chp[9], shp[9];
        chp[0]=1.f; shp[0]=1.f;
        #pragma unroll
        for (int k=1;k<9;k++){ chp[k]=chp[k-1]*ch; shp[k]=shp[k-1]*sh; }

        Trig T;
        T.cat[0]=1.f; T.sat[0]=0.f; T.cgt[0]=1.f; T.sgt[0]=0.f;
        #pragma unroll
        for (int k=1;k<5;k++){
            float c0=T.cat[k-1], s0=T.sat[k-1];
            T.cat[k]=c0*ca - s0*sa;  T.sat[k]=s0*ca + c0*sa;
            float c1=T.cgt[k-1], s1=T.sgt[k-1];
            T.cgt[k]=c1*cg - s1*sg;  T.sgt[k]=s1*cg + c1*sg;
        }

        float* base = sD + el * DPITCH;
        if (slot == 0) {
            DLoopR<0,  0, 0,  1, false>::run(base, chp, shp, T);
            DLoopR<1,  1, 0,  9, false>::run(base, chp, shp, T);
            DLoopR<2, 10, 0, 25, false>::run(base, chp, shp, T);
        } else if (slot == 1) {
            DLoopR<3, 35, 0, 49, false>::run(base, chp, shp, T);
        } else if (slot == 2) {
            DLoopR<4, 84, 0, 40, false>::run(base, chp, shp, T);
        } else {
            DLoopR<4, 84, 40, 81, false>::run(base, chp, shp, T);
        }
    }
    __syncthreads();

    // coalesced flush: 32 consecutive e per k
    const int nE = min(GEPB, E - e0);
    for (int idx = tid; idx < GEPB * NDTOT; idx += 128) {
        int l = idx & (GEPB - 1);
        int k = idx >> 5;
        if (l < nE)
            g_D[(size_t)k * E + e0 + l] = sD[l * DPITCH + k];
    }
}

// ---------------- kernel B: apply block-diagonal D ----------------
template<int L, int B0, int DOFF>
__device__ __forceinline__ void applyL(const float* __restrict__ sDe,
                                       const float* __restrict__ ebase,
                                       float* __restrict__ obase)
{
    constexpr int N1 = 2*L+1;
    float4 eR[N1];
    #pragma unroll
    for (int j=0;j<N1;j++)
        eR[j] = *(const float4*)(ebase + (B0+j)*NCH);
    #pragma unroll
    for (int i=0;i<N1;i++){
        float4 a;
        float d0 = sDe[DOFF + i*N1];
        a.x = d0*eR[0].x; a.y = d0*eR[0].y; a.z = d0*eR[0].z; a.w = d0*eR[0].w;
        #pragma unroll
        for (int j=1;j<N1;j++){
            float d = sDe[DOFF + i*N1 + j];
            a.x = fmaf(d, eR[j].x, a.x);
            a.y = fmaf(d, eR[j].y, a.y);
            a.z = fmaf(d, eR[j].z, a.z);
            a.w = fmaf(d, eR[j].w, a.w);
        }
        *(float4*)(obase + (B0+i)*NCH) = a;
    }
}

__global__ void __launch_bounds__(128)
so3_apply(const float* __restrict__ emb, float* __restrict__ out, int E)
{
    __shared__ float sD[EPB * DPITCH];
    const int tid = threadIdx.x;
    const int e0  = blockIdx.x * EPB;

    // stage D for 8 elements: sD[el][k] = g_D[k*E + e0+el]
    #pragma unroll
    for (int idx = tid; idx < EPB * NDTOT; idx += 128) {
        int el = idx & (EPB - 1);
        int k  = idx >> 3;
        sD[el * DPITCH + k] = g_D[(size_t)k * E + e0 + el];
    }
    __syncthreads();

    const int el     = tid >> 4;          // 0..7
    const int lane16 = tid & 15;          // channels 4*lane16..+3
    const float* sDe = sD + el * DPITCH;
    const size_t off = (size_t)(e0 + el) * ETILE + lane16 * 4;
    const float* eb  = emb + off;
    float*       ob  = out + off;

    applyL<4,16, 84>(sDe, eb, ob);
    applyL<3, 9, 35>(sDe, eb, ob);
    applyL<2, 4, 10>(sDe, eb, ob);
    applyL<1, 1,  1>(sDe, eb, ob);
    applyL<0, 0,  0>(sDe, eb, ob);
}

extern "C" void kernel_launch(void* const* d_in, const int* in_sizes, int n_in,
                              void* d_out, int out_size)
{
    const float* rot = (const float*)d_in[0];   // (E,3,3)
    const float* emb = (const float*)d_in[1];   // (E,25,64)
    float* out = (float*)d_out;                 // (E,25,64)
    int E = in_sizes[0] / 9;
    so3_dgen<<<(E + GEPB - 1) / GEPB, 128>>>(rot, E);
    so3_apply<<<(E + EPB - 1) / EPB, 128>>>(emb, out, E);
}

// round 6
// speedup vs baseline: 1.1160x; 1.0473x over previous
#include <cuda_runtime.h>
#include <math.h>

// SO3_Rotation, two kernels:
//  A) so3_dgen : 32 elements per 128-thread block; lane = element, warp = a
//     cost-balanced contiguous range of the 165 Wigner-D entries. Each entry
//     is computed in closed form (template-unrolled, compile-time coefficients)
//     and written directly to g_D[G*E+e] (coalesced per entry, no smem).
//  B) so3_apply: 8 elements per 128-thread block; each thread owns 4 channels
//     (float4) of one element, computes 25 rows. emb global->reg directly,
//     D broadcast from smem.

#define NROWS 25
#define NCH   64
#define ETILE 1600
#define NDTOT 165
#define EMAX  50048
#define EPB   8
#define GEPB  32
#define DPITCH 166

__device__ float g_D[(size_t)NDTOT * EMAX];

// ---------------- compile-time helpers ----------------
__host__ __device__ constexpr double cfact(int n){ double r=1.0; for(int i=2;i<=n;++i) r*=(double)i; return r; }
__host__ __device__ constexpr double csqrt_(double x){ double r = (x>1.0)?x:1.0; for(int i=0;i<100;++i) r = 0.5*(r + x/r); return r; }
__host__ __device__ constexpr int cmax(int a,int b){ return a>b?a:b; }
__host__ __device__ constexpr int cmin(int a,int b){ return a<b?a:b; }
__host__ __device__ constexpr bool nzB(int x,int y){
    return (x>0&&y>0)||(x<0&&y<0)||(x==0&&y>=0)||(x>0&&y==0);
}
// global D index -> (L, local ij)
__host__ __device__ constexpr int gL(int g){ return g==0?0 : (g<10?1 : (g<35?2 : (g<84?3 : 4))); }
__host__ __device__ constexpr int gOFF(int g){ int l=gL(g); return l==0?0 : (l==1?1 : (l==2?10 : (l==3?35 : 84))); }

template<int L,int P,int Q,int K,bool Done>
struct DTerm {
    static constexpr float coef = (float)(
        ((((P-Q+K)&1)? -1.0 : 1.0) *
         csqrt_(cfact(L+P)*cfact(L-P)*cfact(L+Q)*cfact(L-Q)) /
         (cfact(L+Q-K)*cfact(K)*cfact(P-Q+K)*cfact(L-P-K))));
    __device__ static __forceinline__ float eval(const float* chp, const float* shp){
        constexpr int K1 = cmin(L+Q, L-P);
        return fmaf(coef, chp[2*L+Q-P-2*K]*shp[P-Q+2*K],
                    DTerm<L,P,Q,K+1,(K+1>K1)>::eval(chp,shp));
    }
};
template<int L,int P,int Q,int K>
struct DTerm<L,P,Q,K,true> {
    __device__ static __forceinline__ float eval(const float*, const float*){ return 0.f; }
};

template<int L,int P,int Q>
__device__ __forceinline__ float dval(const float* chp, const float* shp){
    constexpr int K0 = cmax(0, Q-P);
    constexpr int K1 = cmin(L+Q, L-P);
    return DTerm<L,P,Q,K0,(K0>K1)>::eval(chp,shp);
}

template<int L,int X,int Y>
__device__ __forceinline__ float Bval(const float* chp, const float* shp){
    if constexpr (X>0 && Y>0){
        constexpr float s1 = ((X+Y)&1)? -1.f : 1.f;
        constexpr float s2 = (X&1)? -1.f : 1.f;
        return s1*dval<L,X,Y>(chp,shp) + s2*dval<L,X,-Y>(chp,shp);
    } else if constexpr (X<0 && Y<0){
        constexpr int P=-X, Q=-Y;
        constexpr float s1 = ((P+Q)&1)? -1.f : 1.f;
        constexpr float s2 = (P&1)? -1.f : 1.f;
        return s1*dval<L,P,Q>(chp,shp) - s2*dval<L,P,-Q>(chp,shp);
    } else if constexpr (X==0 && Y==0){
        return dval<L,0,0>(chp,shp);
    } else if constexpr (X==0 && Y>0){
        constexpr float s = ((Y&1)? -1.f : 1.f) * 1.41421356237309515f;
        return s*dval<L,0,Y>(chp,shp);
    } else if constexpr (X>0 && Y==0){
        constexpr float s = ((X&1)? -1.f : 1.f) * 1.41421356237309515f;
        return s*dval<L,X,0>(chp,shp);
    } else {
        return 0.f;
    }
}

struct Trig { float cat[5], sat[5], cgt[5], sgt[5]; };

// one D entry at global index G, written to g_D[G*E + e]
template<int G>
__device__ __forceinline__ float Dentry(const float* chp, const float* shp, const Trig& T){
    constexpr int L  = gL(G);
    constexpr int IJ = G - gOFF(G);
    constexpr int N1 = 2*L+1;
    constexpr int I = IJ / N1, J = IJ % N1;
    constexpr int MA = I - L, NB = J - L;
    constexpr int P = MA<0 ? -MA : MA;
    constexpr int Q = NB<0 ? -NB : NB;
    float rc = T.cat[P];
    float rs = (MA>0) ? -T.sat[P] : T.sat[P];
    float cc = T.cgt[Q];
    float cs = (NB>0) ? T.sgt[Q] : -T.sgt[Q];
    float acc = 0.f;
    if constexpr (nzB(MA,NB))
        acc = fmaf(rc*cc, Bval<L,MA,NB>(chp,shp), acc);
    if constexpr (NB!=0){ if constexpr (nzB(MA,-NB))
        acc = fmaf(rc*cs, Bval<L,MA,(NB!=0)?-NB:0>(chp,shp), acc); }
    if constexpr (MA!=0){ if constexpr (nzB(-MA,NB))
        acc = fmaf(rs*cc, Bval<L,(MA!=0)?-MA:0,NB>(chp,shp), acc); }
    if constexpr (MA!=0 && NB!=0){ if constexpr (nzB(-MA,-NB))
        acc = fmaf(rs*cs, Bval<L,(MA!=0)?-MA:0,(NB!=0)?-NB:0>(chp,shp), acc); }
    return acc;
}

template<int G,int END,bool Done>
struct DRange {
    __device__ static __forceinline__ void run(float* __restrict__ gbase, size_t sE,
            const float* chp, const float* shp, const Trig& T){
        gbase[(size_t)G * sE] = Dentry<G>(chp, shp, T);
        DRange<G+1,END,(G+1==END)>::run(gbase, sE, chp, shp, T);
    }
};
template<int G,int END>
struct DRange<G,END,true>{
    __device__ static __forceinline__ void run(float*, size_t, const float*, const float*, const Trig&){}
};

// ---------------- kernel A: build D ----------------
__global__ void __launch_bounds__(128)
so3_dgen(const float* __restrict__ rot, int E)
{
    const int tid  = threadIdx.x;
    const int lane = tid & 31;
    const int w    = tid >> 5;        // 0..3: entry range
    const int e    = blockIdx.x * GEPB + lane;
    if (e >= E) return;

    const float* R = rot + (size_t)e * 9;
    float r00=R[0], r01=R[1], r02=R[2];
    float r11=R[4];
    float r20=R[6], r21=R[7], r22=R[8];

    float x0=r01, x1=r11, x2=r21;
    float inv = rsqrtf(x0*x0 + x1*x1 + x2*x2);
    x0*=inv; x1*=inv; x2*=inv;
    x0 = fminf(1.f, fmaxf(-1.f, x0));
    x1 = fminf(1.f, fmaxf(-1.f, x1));
    x2 = fminf(1.f, fmaxf(-1.f, x2));
    float cb = x1;
    float rxz = sqrtf(x0*x0 + x2*x2);
    float ca, sa;
    if (rxz > 1e-20f){ ca = x2/rxz; sa = x0/rxz; } else { ca = 1.f; sa = 0.f; }
    float gy = ca*r02 - sa*r22;
    float gx = ca*r00 - sa*r20;
    float gr = sqrtf(gx*gx + gy*gy);
    float cg, sg;
    if (gr > 1e-20f){ cg = gx/gr; sg = gy/gr; } else { cg = 1.f; sg = 0.f; }

    float ch = sqrtf(fmaxf(0.f, 0.5f*(1.f+cb)));
    float sh = sqrtf(fmaxf(0.f, 0.5f*(1.f-cb)));
    float chp[9], shp[9];
    chp[0]=1.f; shp[0]=1.f;
    #pragma unroll
    for (int k=1;k<9;k++){ chp[k]=chp[k-1]*ch; shp[k]=shp[k-1]*sh; }

    Trig T;
    T.cat[0]=1.f; T.sat[0]=0.f; T.cgt[0]=1.f; T.sgt[0]=0.f;
    #pragma unroll
    for (int k=1;k<5;k++){
        float c0=T.cat[k-1], s0=T.sat[k-1];
        T.cat[k]=c0*ca - s0*sa;  T.sat[k]=s0*ca + c0*sa;
        float c1=T.cgt[k-1], s1=T.sgt[k-1];
        T.cgt[k]=c1*cg - s1*sg;  T.sgt[k]=s1*cg + c1*sg;
    }

    float* gbase = g_D + e;
    size_t sE = (size_t)E;
    // cost-balanced entry ranges (~equal sum of (2L+1))
    switch (w) {
        case 0: DRange<  0,  57, false>::run(gbase, sE, chp, shp, T); break;
        case 1: DRange< 57,  97, false>::run(gbase, sE, chp, shp, T); break;
        case 2: DRange< 97, 131, false>::run(gbase, sE, chp, shp, T); break;
        default:DRange<131, 165, false>::run(gbase, sE, chp, shp, T); break;
    }
}

// ---------------- kernel B: apply block-diagonal D ----------------
template<int L, int B0, int DOFF>
__device__ __forceinline__ void applyL(const float* __restrict__ sDe,
                                       const float* __restrict__ ebase,
                                       float* __restrict__ obase)
{
    constexpr int N1 = 2*L+1;
    float4 eR[N1];
    #pragma unroll
    for (int j=0;j<N1;j++)
        eR[j] = *(const float4*)(ebase + (B0+j)*NCH);
    #pragma unroll
    for (int i=0;i<N1;i++){
        float4 a;
        float d0 = sDe[DOFF + i*N1];
        a.x = d0*eR[0].x; a.y = d0*eR[0].y; a.z = d0*eR[0].z; a.w = d0*eR[0].w;
        #pragma unroll
        for (int j=1;j<N1;j++){
            float d = sDe[DOFF + i*N1 + j];
            a.x = fmaf(d, eR[j].x, a.x);
            a.y = fmaf(d, eR[j].y, a.y);
            a.z = fmaf(d, eR[j].z, a.z);
            a.w = fmaf(d, eR[j].w, a.w);
        }
        *(float4*)(obase + (B0+i)*NCH) = a;
    }
}

__global__ void __launch_bounds__(128)
so3_apply(const float* __restrict__ emb, float* __restrict__ out, int E)
{
    __shared__ float sD[EPB * DPITCH];
    const int tid = threadIdx.x;
    const int e0  = blockIdx.x * EPB;

    #pragma unroll
    for (int idx = tid; idx < EPB * NDTOT; idx += 128) {
        int el = idx & (EPB - 1);
        int k  = idx >> 3;
        sD[el * DPITCH + k] = g_D[(size_t)k * E + e0 + el];
    }
    __syncthreads();

    const int el     = tid >> 4;
    const int lane16 = tid & 15;
    const float* sDe = sD + el * DPITCH;
    const size_t off = (size_t)(e0 + el) * ETILE + lane16 * 4;
    const float* eb  = emb + off;
    float*       ob  = out + off;

    applyL<4,16, 84>(sDe, eb, ob);
    applyL<3, 9, 35>(sDe, eb, ob);
    applyL<2, 4, 10>(sDe, eb, ob);
    applyL<1, 1,  1>(sDe, eb, ob);
    applyL<0, 0,  0>(sDe, eb, ob);
}

extern "C" void kernel_launch(void* const* d_in, const int* in_sizes, int n_in,
                              void* d_out, int out_size)
{
    const float* rot = (const float*)d_in[0];   // (E,3,3)
    const float* emb = (const float*)d_in[1];   // (E,25,64)
    float* out = (float*)d_out;                 // (E,25,64)
    int E = in_sizes[0] / 9;
    so3_dgen<<<(E + GEPB - 1) / GEPB, 128>>>(rot, E);
    so3_apply<<<(E + EPB - 1) / EPB, 128>>>(emb, out, E);
}

// round 7
// speedup vs baseline: 1.1186x; 1.0023x over previous
#include <cuda_runtime.h>
#include <math.h>

// SO3_Rotation, two kernels:
//  A) so3_dgen : 32 elements per 256-thread block; lane = element, each of the
//     8 warps owns a cost-balanced contiguous range of the 165 Wigner-D
//     entries (closed form, template-unrolled, compile-time coefficients),
//     written directly to g_D[G*E+e] (coalesced per entry).
//  B) so3_apply: 8 elements per 128-thread block; each thread owns 4 channels
//     (float4) of one element, computes 25 rows. emb/out use streaming cache
//     hints (touched once) so the D table stays L2-resident.

#define NROWS 25
#define NCH   64
#define ETILE 1600
#define NDTOT 165
#define EMAX  50048
#define EPB   8
#define GEPB  32
#define DPITCH 166

__device__ float g_D[(size_t)NDTOT * EMAX];

// ---------------- compile-time helpers ----------------
__host__ __device__ constexpr double cfact(int n){ double r=1.0; for(int i=2;i<=n;++i) r*=(double)i; return r; }
__host__ __device__ constexpr double csqrt_(double x){ double r = (x>1.0)?x:1.0; for(int i=0;i<100;++i) r = 0.5*(r + x/r); return r; }
__host__ __device__ constexpr int cmax(int a,int b){ return a>b?a:b; }
__host__ __device__ constexpr int cmin(int a,int b){ return a<b?a:b; }
__host__ __device__ constexpr bool nzB(int x,int y){
    return (x>0&&y>0)||(x<0&&y<0)||(x==0&&y>=0)||(x>0&&y==0);
}
__host__ __device__ constexpr int gL(int g){ return g==0?0 : (g<10?1 : (g<35?2 : (g<84?3 : 4))); }
__host__ __device__ constexpr int gOFF(int g){ int l=gL(g); return l==0?0 : (l==1?1 : (l==2?10 : (l==3?35 : 84))); }

template<int L,int P,int Q,int K,bool Done>
struct DTerm {
    static constexpr float coef = (float)(
        ((((P-Q+K)&1)? -1.0 : 1.0) *
         csqrt_(cfact(L+P)*cfact(L-P)*cfact(L+Q)*cfact(L-Q)) /
         (cfact(L+Q-K)*cfact(K)*cfact(P-Q+K)*cfact(L-P-K))));
    __device__ static __forceinline__ float eval(const float* chp, const float* shp){
        constexpr int K1 = cmin(L+Q, L-P);
        return fmaf(coef, chp[2*L+Q-P-2*K]*shp[P-Q+2*K],
                    DTerm<L,P,Q,K+1,(K+1>K1)>::eval(chp,shp));
    }
};
template<int L,int P,int Q,int K>
struct DTerm<L,P,Q,K,true> {
    __device__ static __forceinline__ float eval(const float*, const float*){ return 0.f; }
};

template<int L,int P,int Q>
__device__ __forceinline__ float dval(const float* chp, const float* shp){
    constexpr int K0 = cmax(0, Q-P);
    constexpr int K1 = cmin(L+Q, L-P);
    return DTerm<L,P,Q,K0,(K0>K1)>::eval(chp,shp);
}

template<int L,int X,int Y>
__device__ __forceinline__ float Bval(const float* chp, const float* shp){
    if constexpr (X>0 && Y>0){
        constexpr float s1 = ((X+Y)&1)? -1.f : 1.f;
        constexpr float s2 = (X&1)? -1.f : 1.f;
        return s1*dval<L,X,Y>(chp,shp) + s2*dval<L,X,-Y>(chp,shp);
    } else if constexpr (X<0 && Y<0){
        constexpr int P=-X, Q=-Y;
        constexpr float s1 = ((P+Q)&1)? -1.f : 1.f;
        constexpr float s2 = (P&1)? -1.f : 1.f;
        return s1*dval<L,P,Q>(chp,shp) - s2*dval<L,P,-Q>(chp,shp);
    } else if constexpr (X==0 && Y==0){
        return dval<L,0,0>(chp,shp);
    } else if constexpr (X==0 && Y>0){
        constexpr float s = ((Y&1)? -1.f : 1.f) * 1.41421356237309515f;
        return s*dval<L,0,Y>(chp,shp);
    } else if constexpr (X>0 && Y==0){
        constexpr float s = ((X&1)? -1.f : 1.f) * 1.41421356237309515f;
        return s*dval<L,X,0>(chp,shp);
    } else {
        return 0.f;
    }
}

struct Trig { float cat[5], sat[5], cgt[5], sgt[5]; };

template<int G>
__device__ __forceinline__ float Dentry(const float* chp, const float* shp, const Trig& T){
    constexpr int L  = gL(G);
    constexpr int IJ = G - gOFF(G);
    constexpr int N1 = 2*L+1;
    constexpr int I = IJ / N1, J = IJ % N1;
    constexpr int MA = I - L, NB = J - L;
    constexpr int P = MA<0 ? -MA : MA;
    constexpr int Q = NB<0 ? -NB : NB;
    float rc = T.cat[P];
    float rs = (MA>0) ? -T.sat[P] : T.sat[P];
    float cc = T.cgt[Q];
    float cs = (NB>0) ? T.sgt[Q] : -T.sgt[Q];
    float acc = 0.f;
    if constexpr (nzB(MA,NB))
        acc = fmaf(rc*cc, Bval<L,MA,NB>(chp,shp), acc);
    if constexpr (NB!=0){ if constexpr (nzB(MA,-NB))
        acc = fmaf(rc*cs, Bval<L,MA,(NB!=0)?-NB:0>(chp,shp), acc); }
    if constexpr (MA!=0){ if constexpr (nzB(-MA,NB))
        acc = fmaf(rs*cc, Bval<L,(MA!=0)?-MA:0,NB>(chp,shp), acc); }
    if constexpr (MA!=0 && NB!=0){ if constexpr (nzB(-MA,-NB))
        acc = fmaf(rs*cs, Bval<L,(MA!=0)?-MA:0,(NB!=0)?-NB:0>(chp,shp), acc); }
    return acc;
}

template<int G,int END,bool Done>
struct DRange {
    __device__ static __forceinline__ void run(float* __restrict__ gbase, size_t sE,
            const float* chp, const float* shp, const Trig& T){
        gbase[(size_t)G * sE] = Dentry<G>(chp, shp, T);
        DRange<G+1,END,(G+1==END)>::run(gbase, sE, chp, shp, T);
    }
};
template<int G,int END>
struct DRange<G,END,true>{
    __device__ static __forceinline__ void run(float*, size_t, const float*, const float*, const Trig&){}
};

// ---------------- kernel A: build D (8 warp-slots, cost-balanced) ----------------
__global__ void __launch_bounds__(256)
so3_dgen(const float* __restrict__ rot, int E)
{
    const int tid  = threadIdx.x;
    const int lane = tid & 31;
    const int w    = tid >> 5;        // 0..7: entry range
    const int e    = blockIdx.x * GEPB + lane;
    if (e >= E) return;

    const float* R = rot + (size_t)e * 9;
    float r00=R[0], r01=R[1], r02=R[2];
    float r11=R[4];
    float r20=R[6], r21=R[7], r22=R[8];

    float x0=r01, x1=r11, x2=r21;
    float inv = rsqrtf(x0*x0 + x1*x1 + x2*x2);
    x0*=inv; x1*=inv; x2*=inv;
    x0 = fminf(1.f, fmaxf(-1.f, x0));
    x1 = fminf(1.f, fmaxf(-1.f, x1));
    x2 = fminf(1.f, fmaxf(-1.f, x2));
    float cb = x1;
    float rxz = sqrtf(x0*x0 + x2*x2);
    float ca, sa;
    if (rxz > 1e-20f){ ca = x2/rxz; sa = x0/rxz; } else { ca = 1.f; sa = 0.f; }
    float gy = ca*r02 - sa*r22;
    float gx = ca*r00 - sa*r20;
    float gr = sqrtf(gx*gx + gy*gy);
    float cg, sg;
    if (gr > 1e-20f){ cg = gx/gr; sg = gy/gr; } else { cg = 1.f; sg = 0.f; }

    float ch = sqrtf(fmaxf(0.f, 0.5f*(1.f+cb)));
    float sh = sqrtf(fmaxf(0.f, 0.5f*(1.f-cb)));
    float chp[9], shp[9];
    chp[0]=1.f; shp[0]=1.f;
    #pragma unroll
    for (int k=1;k<9;k++){ chp[k]=chp[k-1]*ch; shp[k]=shp[k-1]*sh; }

    Trig T;
    T.cat[0]=1.f; T.sat[0]=0.f; T.cgt[0]=1.f; T.sgt[0]=0.f;
    #pragma unroll
    for (int k=1;k<5;k++){
        float c0=T.cat[k-1], s0=T.sat[k-1];
        T.cat[k]=c0*ca - s0*sa;  T.sat[k]=s0*ca + c0*sa;
        float c1=T.cgt[k-1], s1=T.sgt[k-1];
        T.cgt[k]=c1*cg - s1*sg;  T.sgt[k]=s1*cg + c1*sg;
    }

    float* gbase = g_D + e;
    size_t sE = (size_t)E;
    // 8 cost-balanced entry ranges (~153 cost-units each; cost ~ 2L+1)
    switch (w) {
        case 0: DRange<  0,  35, false>::run(gbase, sE, chp, shp, T); break;
        case 1: DRange< 35,  57, false>::run(gbase, sE, chp, shp, T); break;
        case 2: DRange< 57,  79, false>::run(gbase, sE, chp, shp, T); break;
        case 3: DRange< 79,  97, false>::run(gbase, sE, chp, shp, T); break;
        case 4: DRange< 97, 114, false>::run(gbase, sE, chp, shp, T); break;
        case 5: DRange<114, 131, false>::run(gbase, sE, chp, shp, T); break;
        case 6: DRange<131, 148, false>::run(gbase, sE, chp, shp, T); break;
        default:DRange<148, 165, false>::run(gbase, sE, chp, shp, T); break;
    }
}

// ---------------- kernel B: apply block-diagonal D ----------------
template<int L, int B0, int DOFF>
__device__ __forceinline__ void applyL(const float* __restrict__ sDe,
                                       const float* __restrict__ ebase,
                                       float* __restrict__ obase)
{
    constexpr int N1 = 2*L+1;
    float4 eR[N1];
    #pragma unroll
    for (int j=0;j<N1;j++)
        eR[j] = __ldcs((const float4*)(ebase + (B0+j)*NCH));
    #pragma unroll
    for (int i=0;i<N1;i++){
        float4 a;
        float d0 = sDe[DOFF + i*N1];
        a.x = d0*eR[0].x; a.y = d0*eR[0].y; a.z = d0*eR[0].z; a.w = d0*eR[0].w;
        #pragma unroll
        for (int j=1;j<N1;j++){
            float d = sDe[DOFF + i*N1 + j];
            a.x = fmaf(d, eR[j].x, a.x);
            a.y = fmaf(d, eR[j].y, a.y);
            a.z = fmaf(d, eR[j].z, a.z);
            a.w = fmaf(d, eR[j].w, a.w);
        }
        __stcs((float4*)(obase + (B0+i)*NCH), a);
    }
}

__global__ void __launch_bounds__(128)
so3_apply(const float* __restrict__ emb, float* __restrict__ out, int E)
{
    __shared__ float sD[EPB * DPITCH];
    const int tid = threadIdx.x;
    const int e0  = blockIdx.x * EPB;

    #pragma unroll
    for (int idx = tid; idx < EPB * NDTOT; idx += 128) {
        int el = idx & (EPB - 1);
        int k  = idx >> 3;
        sD[el * DPITCH + k] = g_D[(size_t)k * E + e0 + el];
    }
    __syncthreads();

    const int el     = tid >> 4;
    const int lane16 = tid & 15;
    const float* sDe = sD + el * DPITCH;
    const size_t off = (size_t)(e0 + el) * ETILE + lane16 * 4;
    const float* eb  = emb + off;
    float*       ob  = out + off;

    applyL<4,16, 84>(sDe, eb, ob);
    applyL<3, 9, 35>(sDe, eb, ob);
    applyL<2, 4, 10>(sDe, eb, ob);
    applyL<1, 1,  1>(sDe, eb, ob);
    applyL<0, 0,  0>(sDe, eb, ob);
}

extern "C" void kernel_launch(void* const* d_in, const int* in_sizes, int n_in,
                              void* d_out, int out_size)
{
    const float* rot = (const float*)d_in[0];   // (E,3,3)
    const float* emb = (const float*)d_in[1];   // (E,25,64)
    float* out = (float*)d_out;                 // (E,25,64)
    int E = in_sizes[0] / 9;
    so3_dgen<<<(E + GEPB - 1) / GEPB, 256>>>(rot, E);
    so3_apply<<<(E + EPB - 1) / EPB, 128>>>(emb, out, E);
}